// round 1
// baseline (speedup 1.0000x reference)
#include <cuda_runtime.h>

#define T_STEPS 2048
#define BATCH   256
#define HID     64
#define NG      256   // 4 * HID gates
#define NOUT    11

// Inter-layer hidden-state buffers ([B][T][HID]) + final hidden state.
__device__ float g_buf0[(size_t)BATCH * T_STEPS * HID];
__device__ float g_buf1[(size_t)BATCH * T_STEPS * HID];
__device__ float g_hfin[BATCH * HID];

__device__ __forceinline__ float sig_(float x) { return 1.0f / (1.0f + __expf(-x)); }

// One LSTM layer. Each CTA owns 2 batch elements and runs the full T-step
// recurrence locally (batch elements are independent -> no global sync).
// Thread g keeps its combined weight row [W_ih[g] | W_hh[g]] in registers.
// LIDX selects input/output buffers: 0: x -> g_buf0, 1: g_buf0 -> g_buf1,
// 2: g_buf1 -> g_hfin (last timestep only).
template<int KIN, int LIDX>
__global__ __launch_bounds__(256, 1)
void lstm_layer_kernel(const float* __restrict__ x_in,
                       const float* __restrict__ W_ih,
                       const float* __restrict__ W_hh,
                       const float* __restrict__ b_ih,
                       const float* __restrict__ b_hh)
{
    constexpr int KTOT = KIN + HID;
    constexpr int KPAD = (KTOT + 3) & ~3;

    __shared__ __align__(16) float v[2][KPAD];   // [x_t | h_{t-1}] per batch elem
    __shared__ float gates[2][NG];

    const float* in_seq = (LIDX == 0) ? x_in : (LIDX == 1 ? g_buf0 : g_buf1);

    const int tid = threadIdx.x;       // gate row 0..255
    const int b0  = blockIdx.x * 2;

    // Load weight row into registers (one-time, 64KB/layer total, L1-cached).
    float w[KPAD];
#pragma unroll
    for (int k = 0; k < KPAD; k++) w[k] = 0.0f;
#pragma unroll
    for (int k = 0; k < KIN; k++) w[k] = W_ih[tid * KIN + k];
#pragma unroll
    for (int k = 0; k < HID; k++) w[KIN + k] = W_hh[tid * HID + k];
    const float bias = b_ih[tid] + b_hh[tid];

    // Zero h region + padding of v (x region is rewritten every step).
    for (int i = tid; i < 2 * KPAD; i += 256) {
        int be = i / KPAD, k = i - be * KPAD;
        if (k >= KIN) v[be][k] = 0.0f;
    }

    const int pbe = tid >> 6;          // pointwise: which batch elem
    const int pj  = tid & 63;          // pointwise: hidden index
    const bool pw  = (tid < 128);
    const bool ldx = pw && (pj < KIN);

    float c  = 0.0f;                   // cell state (pointwise threads only)
    float xr = 0.0f;                   // prefetched next-step input
    const size_t in_base = (size_t)(b0 + pbe) * T_STEPS * KIN + pj;
    if (ldx) xr = in_seq[in_base];

    for (int t = 0; t < T_STEPS; t++) {
        if (ldx) v[pbe][pj] = xr;
        __syncthreads();               // v (x part + h from prev step) ready
        if (ldx && (t + 1 < T_STEPS))
            xr = in_seq[in_base + (size_t)(t + 1) * KIN];  // prefetch, hidden by compute

        float a0[4], a1[4];
#pragma unroll
        for (int u = 0; u < 4; u++) { a0[u] = 0.0f; a1[u] = 0.0f; }
        const float4* v0 = reinterpret_cast<const float4*>(v[0]);
        const float4* v1 = reinterpret_cast<const float4*>(v[1]);
#pragma unroll
        for (int k4 = 0; k4 < KPAD / 4; k4++) {
            float4 p = v0[k4];         // broadcast LDS.128, conflict-free
            float4 q = v1[k4];
            a0[0] += w[4*k4+0] * p.x;  a0[1] += w[4*k4+1] * p.y;
            a0[2] += w[4*k4+2] * p.z;  a0[3] += w[4*k4+3] * p.w;
            a1[0] += w[4*k4+0] * q.x;  a1[1] += w[4*k4+1] * q.y;
            a1[2] += w[4*k4+2] * q.z;  a1[3] += w[4*k4+3] * q.w;
        }
        gates[0][tid] = (a0[0] + a0[1]) + (a0[2] + a0[3]) + bias;
        gates[1][tid] = (a1[0] + a1[1]) + (a1[2] + a1[3]) + bias;
        __syncthreads();               // gates ready

        if (pw) {
            float gi = gates[pbe][pj];
            float gf = gates[pbe][64 + pj];
            float gg = gates[pbe][128 + pj];
            float go = gates[pbe][192 + pj];
            c = sig_(gf) * c + sig_(gi) * tanhf(gg);
            float h = sig_(go) * tanhf(c);
            v[pbe][KIN + pj] = h;      // feed next step (visible after top barrier)
            if (LIDX == 0)
                g_buf0[(size_t)(b0 + pbe) * T_STEPS * HID + (size_t)t * HID + pj] = h;
            else if (LIDX == 1)
                g_buf1[(size_t)(b0 + pbe) * T_STEPS * HID + (size_t)t * HID + pj] = h;
            else if (t == T_STEPS - 1)
                g_hfin[(b0 + pbe) * HID + pj] = h;
        }
    }
}

__global__ void final_linear_kernel(const float* __restrict__ W_out,
                                    const float* __restrict__ b_out,
                                    float* __restrict__ out)
{
    int idx = blockIdx.x * blockDim.x + threadIdx.x;
    if (idx >= BATCH * NOUT) return;
    int b = idx / NOUT, o = idx - b * NOUT;
    float s = b_out[o];
    const float* h  = &g_hfin[b * HID];
    const float* wr = &W_out[o * HID];
#pragma unroll 16
    for (int j = 0; j < HID; j++) s += h[j] * wr[j];
    out[idx] = s;
}

extern "C" void kernel_launch(void* const* d_in, const int* in_sizes, int n_in,
                              void* d_out, int out_size)
{
    const float* x    = (const float*)d_in[0];
    const float* Wih0 = (const float*)d_in[1];
    const float* Whh0 = (const float*)d_in[2];
    const float* bih0 = (const float*)d_in[3];
    const float* bhh0 = (const float*)d_in[4];
    const float* Wih1 = (const float*)d_in[5];
    const float* Whh1 = (const float*)d_in[6];
    const float* bih1 = (const float*)d_in[7];
    const float* bhh1 = (const float*)d_in[8];
    const float* Wih2 = (const float*)d_in[9];
    const float* Whh2 = (const float*)d_in[10];
    const float* bih2 = (const float*)d_in[11];
    const float* bhh2 = (const float*)d_in[12];
    const float* Wout = (const float*)d_in[13];
    const float* bout = (const float*)d_in[14];

    dim3 grid(BATCH / 2), block(256);
    lstm_layer_kernel<2,  0><<<grid, block>>>(x,       Wih0, Whh0, bih0, bhh0);
    lstm_layer_kernel<64, 1><<<grid, block>>>(nullptr, Wih1, Whh1, bih1, bhh1);
    lstm_layer_kernel<64, 2><<<grid, block>>>(nullptr, Wih2, Whh2, bih2, bhh2);
    final_linear_kernel<<<(BATCH * NOUT + 255) / 256, 256>>>(Wout, bout, (float*)d_out);
}

// round 2
// speedup vs baseline: 1.1882x; 1.1882x over previous
#include <cuda_runtime.h>

#define T_STEPS 2048
#define BATCH   256
#define HID     64
#define NG      256   // 4 * HID gates
#define NOUT    11

typedef unsigned long long u64;

// Inter-layer hidden-state buffers ([B][T][HID]) + final hidden state.
__device__ float g_buf0[(size_t)BATCH * T_STEPS * HID];
__device__ float g_buf1[(size_t)BATCH * T_STEPS * HID];
__device__ float g_hfin[BATCH * HID];

__device__ __forceinline__ u64 pack2(float a, float b) {
    u64 r; asm("mov.b64 %0, {%1,%2};" : "=l"(r) : "f"(a), "f"(b)); return r;
}
__device__ __forceinline__ void unpack2(u64 v, float& a, float& b) {
    asm("mov.b64 {%0,%1}, %2;" : "=f"(a), "=f"(b) : "l"(v));
}
// d = a*b + d, elementwise on packed f32 pairs (SASS FFMA2: 2 MACs/issue)
__device__ __forceinline__ void ffma2(u64& d, u64 a, u64 b) {
    asm("fma.rn.f32x2 %0, %1, %2, %0;" : "+l"(d) : "l"(a), "l"(b));
}

__device__ __forceinline__ float sigf(float x) {
    return __fdividef(1.0f, 1.0f + __expf(-x));
}
__device__ __forceinline__ float tanh2(float x) {   // 2*sig(2x)-1, err ~1e-6
    return 2.0f * sigf(2.0f * x) - 1.0f;
}

// One LSTM layer. CTA = 2 batch elems, full T recurrence (batch independent).
// Thread g holds W_hh row g (+ W_ih row g) as packed f32x2 register pairs.
// Per step: ph1 h-matmul -> gates STS -> stage x_{t+1} -> bar ->
//           ph4 pointwise (128 thr) overlapped with x-matmul for t+1 -> bar.
template<int KIN, int LIDX>
__global__ __launch_bounds__(256, 1)
void lstm_f32x2_kernel(const float* __restrict__ x_in,
                       const float* __restrict__ W_ih,
                       const float* __restrict__ W_hh,
                       const float* __restrict__ b_ih,
                       const float* __restrict__ b_hh)
{
    __shared__ __align__(16) float sh[2][HID];   // h_{t-1}
    __shared__ __align__(16) float sx[2][KIN];   // x_t staging
    __shared__ float sg[2][NG];                  // gate pre-activations

    const float* in_seq  = (LIDX == 0) ? x_in   : (LIDX == 1 ? g_buf0 : g_buf1);
    float*       out_seq = (LIDX == 0) ? g_buf0 : (LIDX == 1 ? g_buf1 : nullptr);

    const int tid = threadIdx.x;     // gate row 0..255
    const int b0  = blockIdx.x * 2;

    // ---- weights into registers, packed as f32x2 ----
    u64 wh[HID / 2];
#pragma unroll
    for (int k = 0; k < HID / 2; k++)
        wh[k] = pack2(W_hh[tid * HID + 2 * k], W_hh[tid * HID + 2 * k + 1]);
    u64 wx[KIN / 2];
#pragma unroll
    for (int k = 0; k < KIN / 2; k++)
        wx[k] = pack2(W_ih[tid * KIN + 2 * k], W_ih[tid * KIN + 2 * k + 1]);
    const float bias = b_ih[tid] + b_hh[tid];

    const int  pbe = (tid >> 6) & 1;        // batch-elem for pw / ldx roles
    const int  pj  = tid & 63;
    const bool pw  = (tid < 128);           // pointwise threads (warps 0-3)
    const bool ldx = (tid >= 128) && (pj < KIN);  // x loaders (warps 4-7)

    const size_t in_base  = (size_t)(b0 + pbe) * T_STEPS * KIN + pj;
    const size_t out_base = (size_t)(b0 + pbe) * T_STEPS * HID + pj;

    // ---- priming: h_{-1}=0, stage x_0, prefetch x_1 ----
    if (pw) sh[pbe][pj] = 0.0f;
    float xr = 0.0f;
    if (ldx) {
        sx[pbe][pj] = in_seq[in_base];
        xr = in_seq[in_base + KIN];          // x_1 (T>=2)
    }
    __syncthreads();

    // x-part of the gate dot-product, from sx (both batch elems)
    auto xmm = [&](float& r0, float& r1) {
        if constexpr (KIN == 2) {
            u64 t0 = 0ULL, t1 = 0ULL;
            ffma2(t0, *(const u64*)sx[0], wx[0]);
            ffma2(t1, *(const u64*)sx[1], wx[0]);
            float a, b; unpack2(t0, a, b); r0 = a + b;
            unpack2(t1, a, b); r1 = a + b;
        } else {
            u64 s0 = 0ULL, s1 = 0ULL, s2 = 0ULL, s3 = 0ULL;
            const ulonglong2* X0 = (const ulonglong2*)sx[0];
            const ulonglong2* X1 = (const ulonglong2*)sx[1];
#pragma unroll
            for (int k = 0; k < KIN / 4; k++) {
                ulonglong2 p = X0[k], q = X1[k];
                ffma2(s0, p.x, wx[2 * k]); ffma2(s1, p.y, wx[2 * k + 1]);
                ffma2(s2, q.x, wx[2 * k]); ffma2(s3, q.y, wx[2 * k + 1]);
            }
            float a, b, c, d;
            unpack2(s0, a, b); unpack2(s1, c, d); r0 = (a + b) + (c + d);
            unpack2(s2, a, b); unpack2(s3, c, d); r1 = (a + b) + (c + d);
        }
    };

    float xg0, xg1;                 // x-part of gates for current step
    xmm(xg0, xg1);                  // for t = 0

    float c = 0.0f;                 // cell state (pw threads)

    for (int t = 0; t < T_STEPS; t++) {
        // ---- ph1: h-part of gates (h_{t-1} in sh) ----
        u64 a0 = 0ULL, a1 = 0ULL, a2 = 0ULL, a3 = 0ULL;
        const ulonglong2* H0 = (const ulonglong2*)sh[0];
        const ulonglong2* H1 = (const ulonglong2*)sh[1];
#pragma unroll
        for (int k = 0; k < HID / 4; k++) {
            ulonglong2 p = H0[k], q = H1[k];      // broadcast LDS.128
            ffma2(a0, p.x, wh[2 * k]); ffma2(a1, p.y, wh[2 * k + 1]);
            ffma2(a2, q.x, wh[2 * k]); ffma2(a3, q.y, wh[2 * k + 1]);
        }
        {
            float a, b, cc, d;
            unpack2(a0, a, b); unpack2(a1, cc, d);
            sg[0][tid] = xg0 + bias + (a + b) + (cc + d);
            unpack2(a2, a, b); unpack2(a3, cc, d);
            sg[1][tid] = xg1 + bias + (a + b) + (cc + d);
        }
        // ---- ph3: stage x_{t+1}, prefetch x_{t+2} ----
        if (ldx) {
            if (t + 1 < T_STEPS) sx[pbe][pj] = xr;
            xr = (t + 2 < T_STEPS) ? in_seq[in_base + (size_t)(t + 2) * KIN] : 0.0f;
        }
        __syncthreads();    // gates + x_{t+1} visible

        // ---- ph4: pointwise (warps 0-3) overlapped with x-matmul for t+1 ----
        if (pw) {
            float gi = sg[pbe][pj];
            float gf = sg[pbe][64 + pj];
            float gg = sg[pbe][128 + pj];
            float go = sg[pbe][192 + pj];
            c = sigf(gf) * c + sigf(gi) * tanh2(gg);
            float h = sigf(go) * tanh2(c);
            sh[pbe][pj] = h;
            if (LIDX < 2)
                out_seq[out_base + (size_t)t * HID] = h;
            else if (t == T_STEPS - 1)
                g_hfin[(b0 + pbe) * HID + pj] = h;
        }
        if (t + 1 < T_STEPS) xmm(xg0, xg1);   // x-part for next step
        __syncthreads();    // sh (h_t) ready; sx consumable next iter
    }
}

__global__ void final_linear_kernel(const float* __restrict__ W_out,
                                    const float* __restrict__ b_out,
                                    float* __restrict__ out)
{
    int idx = blockIdx.x * blockDim.x + threadIdx.x;
    if (idx >= BATCH * NOUT) return;
    int b = idx / NOUT, o = idx - b * NOUT;
    float s = b_out[o];
    const float* h  = &g_hfin[b * HID];
    const float* wr = &W_out[o * HID];
#pragma unroll 16
    for (int j = 0; j < HID; j++) s += h[j] * wr[j];
    out[idx] = s;
}

extern "C" void kernel_launch(void* const* d_in, const int* in_sizes, int n_in,
                              void* d_out, int out_size)
{
    const float* x    = (const float*)d_in[0];
    const float* Wih0 = (const float*)d_in[1];
    const float* Whh0 = (const float*)d_in[2];
    const float* bih0 = (const float*)d_in[3];
    const float* bhh0 = (const float*)d_in[4];
    const float* Wih1 = (const float*)d_in[5];
    const float* Whh1 = (const float*)d_in[6];
    const float* bih1 = (const float*)d_in[7];
    const float* bhh1 = (const float*)d_in[8];
    const float* Wih2 = (const float*)d_in[9];
    const float* Whh2 = (const float*)d_in[10];
    const float* bih2 = (const float*)d_in[11];
    const float* bhh2 = (const float*)d_in[12];
    const float* Wout = (const float*)d_in[13];
    const float* bout = (const float*)d_in[14];

    dim3 grid(BATCH / 2), block(256);
    lstm_f32x2_kernel<2,  0><<<grid, block>>>(x,       Wih0, Whh0, bih0, bhh0);
    lstm_f32x2_kernel<64, 1><<<grid, block>>>(nullptr, Wih1, Whh1, bih1, bhh1);
    lstm_f32x2_kernel<64, 2><<<grid, block>>>(nullptr, Wih2, Whh2, bih2, bhh2);
    final_linear_kernel<<<(BATCH * NOUT + 255) / 256, 256>>>(Wout, bout, (float*)d_out);
}